// round 4
// baseline (speedup 1.0000x reference)
#include <cuda_runtime.h>
#include <cuda_bf16.h>

// ---------------------------------------------------------------------------
// Encoder: B=2048 rows of (16 x 512) fp32 state, 2 layers of
//   [LN -> patchify -> qkv dwconv(s2)+BN+pw -> attention(32x32) -> c1d -> lin -> +res]
//   [LN -> patchify -> f1(32->128)+ReLU -> dw3x3+BN+pw(128->128)+ReLU -> f2(128->32) -> +res]
// One CTA per batch row; everything fused in shared memory.
// ---------------------------------------------------------------------------

#define NB      2048
#define LAYERS  2
#define DM      512
#define EPSLN   1e-5f
#define NT      256

// ---- shared memory layout (float offsets) ----
// persistent:
//   SX    [0, 8192)                  : x state 16x512
// attention phase (scratch base 8192):
//   SXP   8192  (32*256 = 8192)      : patches of LN1(x)
//   STMP  16384 (32*64  = 2048)      : dwconv+BN output (per qkv i)
//   SQ    18432 (32*65  = 2080)
//   SK    20512 (32*65)
//   SV    22592 (32*65)
//   SO    24672 (32*65)              : attention output
//   SO16  26752 (16*257 = 4112)      : after c1d          -> end 30864
//   WT    8192  (512*33 = 16896)     : lin_w tile (overlays SXP..SO, all dead) -> end 25088
// ffn phase:
//   ST1   8192 as bf16, 128 rows * 260 cols  = 16640 floats -> end 24832
//   SXP2  24832 (32*256 = 8192)      -> end 33024  (dead after f1)
//   SW1   33024 (128*32 = 4096)      -> end 37120  (dead after f1)
//   SFPW  24832 (128*128 = 16384)    -> end 41216  (loaded after f1)
//   ST2   41216 (128*34 = 4352)      -> end 45568
//   ST3   45568 (128*33 = 4224)      -> end 49792
//   SF2   49792 (32*128 = 4096)      -> end 53888
//   SFDW  53888 (128*12 = 1536)      -> end 55424
#define OFF_SX    0
#define OFF_SXP   8192
#define OFF_STMP  16384
#define OFF_SQ    18432
#define OFF_SK    20512
#define OFF_SV    22592
#define OFF_SO    24672
#define OFF_SO16  26752
#define OFF_WT    8192
#define OFF_ST1   8192
#define OFF_SXP2  24832
#define OFF_SW1   33024
#define OFF_SFPW  24832
#define OFF_ST2   41216
#define OFF_ST3   45568
#define OFF_SF2   49792
#define OFF_SFDW  53888
#define SMEM_FLOATS 55424
#define SMEM_BYTES  (SMEM_FLOATS * 4)

struct Params {
    const float *x;
    const float *ln1_g, *ln1_b, *ln2_g, *ln2_b;
    const float *qkv_dw, *qkv_bng, *qkv_bnb, *qkv_bnm, *qkv_bnv, *qkv_pw;
    const float *position, *c1d_w, *c1d_b, *lin_w, *lin_b;
    const float *f1_w, *f1_b, *fdw_w, *fdw_b;
    const float *f_bng, *f_bnb, *f_bnm, *f_bnv;
    const float *fpw_w, *fpw_b, *f2_w, *f2_b;
    float *out;
};

__device__ __forceinline__ float warp_sum(float v) {
#pragma unroll
    for (int o = 16; o; o >>= 1) v += __shfl_xor_sync(0xffffffffu, v, o);
    return v;
}
__device__ __forceinline__ float warp_max(float v) {
#pragma unroll
    for (int o = 16; o; o >>= 1) v = fmaxf(v, __shfl_xor_sync(0xffffffffu, v, o));
    return v;
}

// LayerNorm over the 512-feature rows of sx, scattered into patch layout:
// dst[d*256 + h*16 + p2] = LN(sx[h][d*16+p2]) * g[j] + b[j],  j = d*16+p2
__device__ __forceinline__ void ln_to_patches(const float* sx, float* dst,
                                              const float* g, const float* bb,
                                              int lane, int wid) {
#pragma unroll
    for (int r = 0; r < 2; r++) {
        int h = wid + 8 * r;
        float s = 0.f, ss = 0.f;
#pragma unroll
        for (int i = 0; i < 16; i++) {
            float v = sx[h * 512 + lane + 32 * i];
            s += v; ss += v * v;
        }
        s = warp_sum(s); ss = warp_sum(ss);
        float mean = s * (1.f / 512.f);
        float var = ss * (1.f / 512.f) - mean * mean;
        float rs = rsqrtf(var + EPSLN);
#pragma unroll
        for (int i = 0; i < 16; i++) {
            int j = lane + 32 * i;
            float v = (sx[h * 512 + j] - mean) * rs * g[j] + bb[j];
            dst[(j >> 4) * 256 + h * 16 + (j & 15)] = v;
        }
    }
}

extern __shared__ float sm[];

__global__ void __launch_bounds__(NT, 1) encoder_kernel(Params p) {
    const int b = blockIdx.x;
    const int tid = threadIdx.x;
    const int lane = tid & 31;
    const int wid = tid >> 5;

    float* sx = sm + OFF_SX;

    // ---- load x (16x512) ----
    {
        const float4* xg = (const float4*)(p.x + (size_t)b * 8192);
        float4* sx4 = (float4*)sx;
#pragma unroll
        for (int it = 0; it < 8; it++) sx4[tid + NT * it] = xg[tid + NT * it];
    }
    __syncthreads();

    for (int l = 0; l < LAYERS; l++) {
        // ================= attention sublayer =================
        ln_to_patches(sx, sm + OFF_SXP, p.ln1_g + l * DM, p.ln1_b + l * DM, lane, wid);
        __syncthreads();

        // ---- q/k/v: depthwise 3x3 s2 + BN + 1x1 pointwise ----
        for (int i = 0; i < 3; i++) {
            const float* sxp = sm + OFF_SXP;
            float* stmp = sm + OFF_STMP;
            const float* dw  = p.qkv_dw  + (size_t)((l * 3 + i) * 32) * 9;
            const float* bng = p.qkv_bng + (l * 3 + i) * 32;
            const float* bnb = p.qkv_bnb + (l * 3 + i) * 32;
            const float* bnm = p.qkv_bnm + (l * 3 + i) * 32;
            const float* bnv = p.qkv_bnv + (l * 3 + i) * 32;
#pragma unroll 2
            for (int it = 0; it < 8; it++) {
                int u = tid + NT * it;
                int c = u >> 6, pos = u & 63;
                int oh = pos >> 3, ow = pos & 7;
                int ch2 = 2 * oh, cw2 = 2 * ow;
                const float* wp = dw + c * 9;
                float acc = 0.f;
#pragma unroll
                for (int kh = 0; kh < 3; kh++) {
                    int ih = ch2 - 1 + kh;
                    if ((unsigned)ih < 16u) {
#pragma unroll
                        for (int kw = 0; kw < 3; kw++) {
                            int iw = cw2 - 1 + kw;
                            if ((unsigned)iw < 16u)
                                acc += sxp[c * 256 + ih * 16 + iw] * wp[kh * 3 + kw];
                        }
                    }
                }
                float sc = bng[c] * rsqrtf(bnv[c] + EPSLN);
                float sh = bnb[c] - bnm[c] * sc;
                stmp[c * 64 + pos] = acc * sc + sh;
            }
            __syncthreads();
            // pointwise 32->32
            const float* pw = p.qkv_pw + (size_t)((l * 3 + i) * 32) * 32;
            float* dstq = sm + OFF_SQ + i * 2080;
#pragma unroll 2
            for (int it = 0; it < 8; it++) {
                int u = tid + NT * it;
                int d = u >> 6, pos = u & 63;
                const float* w = pw + d * 32;
                float acc = 0.f;
#pragma unroll
                for (int c = 0; c < 32; c++) acc += stmp[c * 64 + pos] * w[c];
                dstq[d * 65 + pos] = acc;
            }
            __syncthreads();
        }

        // ---- attention: scores + softmax + weighted V ----
        {
            float* sq = sm + OFF_SQ;
            float* sk = sm + OFF_SK;
            float* sv = sm + OFF_SV;
            float* so = sm + OFF_SO;
            const float* posw = p.position + l * 1024;
#pragma unroll
            for (int r = 0; r < 4; r++) {
                int d = wid + 8 * r;
                const float* qd = sq + d * 65;
                const float* kf = sk + lane * 65;
                float s = 0.f;
#pragma unroll
                for (int e = 0; e < 64; e++) s += qd[e] * kf[e];
                s = s * 0.125f + posw[d * 32 + lane];
                float m = warp_max(s);
                float pe = __expf(s - m);
                float den = warp_sum(pe);
                float pr = pe / den;
                float a0 = 0.f, a1 = 0.f;
#pragma unroll
                for (int f = 0; f < 32; f++) {
                    float pf = __shfl_sync(0xffffffffu, pr, f);
                    a0 += pf * sv[f * 65 + lane];
                    a1 += pf * sv[f * 65 + lane + 32];
                }
                so[d * 65 + lane] = a0;
                so[d * 65 + lane + 32] = a1;
            }
        }
        __syncthreads();

        // ---- c1d: (8 -> 16) over "rows", cols = d*8+p2 (256) ----
        {
            float* so = sm + OFF_SO;
            float* so16 = sm + OFF_SO16;
            int col = tid;
            int d = col >> 3, p2 = col & 7;
            float vals[8];
#pragma unroll
            for (int c = 0; c < 8; c++) vals[c] = so[d * 65 + c * 8 + p2];
            const float* w = p.c1d_w + l * 128;
            const float* bb = p.c1d_b + l * 16;
#pragma unroll
            for (int o = 0; o < 16; o++) {
                float acc = bb[o];
#pragma unroll
                for (int c = 0; c < 8; c++) acc += w[o * 8 + c] * vals[c];
                so16[o * 257 + col] = acc;
            }
        }
        __syncthreads();

        // ---- lin: out[c16][o512] = sum_d so16[c][d] * lin_w[o][d]; x += out ----
        {
            float* wt = sm + OFF_WT;
            float* so16 = sm + OFF_SO16;
            const float* lw = p.lin_w + (size_t)l * 131072;
            float acc[16][2];
#pragma unroll
            for (int c = 0; c < 16; c++) { acc[c][0] = 0.f; acc[c][1] = 0.f; }
            const int oa = tid, ob = tid + 256;
            for (int db = 0; db < 8; db++) {
                int d0 = db * 32;
                // stage 512x32 weight tile (coalesced float4)
#pragma unroll
                for (int it = 0; it < 16; it++) {
                    int e4 = tid + NT * it;          // 0..4095
                    int o = e4 >> 3, dd4 = (e4 & 7) * 4;
                    float4 v = *(const float4*)(lw + o * 256 + d0 + dd4);
                    float* w = wt + o * 33 + dd4;
                    w[0] = v.x; w[1] = v.y; w[2] = v.z; w[3] = v.w;
                }
                __syncthreads();
#pragma unroll 4
                for (int dd = 0; dd < 32; dd++) {
                    int d = d0 + dd;
                    float wa = wt[oa * 33 + dd];
                    float wb = wt[ob * 33 + dd];
#pragma unroll
                    for (int c = 0; c < 16; c++) {
                        float s = so16[c * 257 + d];
                        acc[c][0] += s * wa;
                        acc[c][1] += s * wb;
                    }
                }
                __syncthreads();
            }
            const float* lb = p.lin_b + l * 512;
            float ba = lb[oa], bv = lb[ob];
#pragma unroll
            for (int c = 0; c < 16; c++) {
                sx[c * 512 + oa] += acc[c][0] + ba;
                sx[c * 512 + ob] += acc[c][1] + bv;
            }
        }
        __syncthreads();

        // ================= conv-FFN sublayer =================
        ln_to_patches(sx, sm + OFF_SXP2, p.ln2_g + l * DM, p.ln2_b + l * DM, lane, wid);
        // preload f1 weights
        {
            float* sw1 = sm + OFF_SW1;
            const float* w = p.f1_w + l * 4096;
#pragma unroll
            for (int it = 0; it < 16; it++) sw1[tid + NT * it] = w[tid + NT * it];
        }
        __syncthreads();

        // ---- f1: 32->128 + ReLU, store bf16 t1[c][pos] ----
        {
            __nv_bfloat16* st1 = (__nv_bfloat16*)(sm + OFF_ST1);
            float* sxp2 = sm + OFF_SXP2;
            float* sw1 = sm + OFF_SW1;
            const float* f1b = p.f1_b + l * 128;
            float sv_[32];
#pragma unroll
            for (int i = 0; i < 32; i++) sv_[i] = sxp2[i * 256 + tid];
            for (int c0 = 0; c0 < 128; c0 += 4) {
                float a[4];
#pragma unroll
                for (int j = 0; j < 4; j++) a[j] = f1b[c0 + j];
#pragma unroll
                for (int i = 0; i < 32; i++) {
                    float s = sv_[i];
#pragma unroll
                    for (int j = 0; j < 4; j++) a[j] += s * sw1[(c0 + j) * 32 + i];
                }
#pragma unroll
                for (int j = 0; j < 4; j++)
                    st1[(c0 + j) * 260 + tid] = __float2bfloat16(fmaxf(a[j], 0.f));
            }
        }
        __syncthreads();

        // ---- load fpw / f2 / folded dw weights ----
        {
            float* sfpw = sm + OFF_SFPW;
            const float* w = p.fpw_w + (size_t)l * 16384;
#pragma unroll
            for (int it = 0; it < 64; it++) sfpw[tid + NT * it] = w[tid + NT * it];
            float* sf2 = sm + OFF_SF2;
            const float* w2 = p.f2_w + l * 4096;
#pragma unroll
            for (int it = 0; it < 16; it++) sf2[tid + NT * it] = w2[tid + NT * it];
            float* sfdw = sm + OFF_SFDW;
            if (tid < 128) {
                int c = tid;
                const float* dwp = p.fdw_w + l * 1152 + c * 9;
#pragma unroll
                for (int k = 0; k < 9; k++) sfdw[c * 12 + k] = dwp[k];
                float sc = p.f_bng[l * 128 + c] * rsqrtf(p.f_bnv[l * 128 + c] + EPSLN);
                sfdw[c * 12 + 9] = sc;
                sfdw[c * 12 + 10] = (p.fdw_b[l * 128 + c] - p.f_bnm[l * 128 + c]) * sc
                                    + p.f_bnb[l * 128 + c];
            }
        }
        __syncthreads();

        // ---- fused dw3x3+BN -> fpw+ReLU -> f2 -> residual, 2 rows at a time ----
        {
            __nv_bfloat16* st1 = (__nv_bfloat16*)(sm + OFF_ST1);
            float* sfpw = sm + OFF_SFPW;
            float* st2 = sm + OFF_ST2;
            float* st3 = sm + OFF_ST3;
            float* sf2 = sm + OFF_SF2;
            float* sfdw = sm + OFF_SFDW;
            const float* fpwb = p.fpw_b + l * 128;
            const float* f2b = p.f2_b + l * 32;

            for (int hb = 0; hb < 8; hb++) {
                int h0 = hb * 2;
                // (a) depthwise 3x3 s1 + BN on rows h0,h0+1 -> st2[c][32]
#pragma unroll 4
                for (int it = 0; it < 16; it++) {
                    int u = tid + NT * it;
                    int c = u >> 5, ppos = u & 31;
                    int rr = ppos >> 4, w = ppos & 15;
                    int h = h0 + rr;
                    const float* fw = sfdw + c * 12;
                    float acc = 0.f;
#pragma unroll
                    for (int kh = 0; kh < 3; kh++) {
                        int ih = h - 1 + kh;
                        if ((unsigned)ih < 16u) {
#pragma unroll
                            for (int kw = 0; kw < 3; kw++) {
                                int iw = w - 1 + kw;
                                if ((unsigned)iw < 16u)
                                    acc += __bfloat162float(st1[c * 260 + ih * 16 + iw])
                                           * fw[kh * 3 + kw];
                            }
                        }
                    }
                    st2[c * 34 + ppos] = acc * fw[9] + fw[10];
                }
                __syncthreads();

                // (b) fpw 128->128 + ReLU -> st3
                {
                    int p0 = tid & 15, p1 = p0 + 16;
                    int oblk = tid >> 4;       // 0..15, 8 outputs each
                    float a0[8], a1[8];
#pragma unroll
                    for (int j = 0; j < 8; j++) {
                        float bv = fpwb[oblk * 8 + j];
                        a0[j] = bv; a1[j] = bv;
                    }
#pragma unroll 4
                    for (int c = 0; c < 128; c++) {
                        float s0 = st2[c * 34 + p0];
                        float s1 = st2[c * 34 + p1];
#pragma unroll
                        for (int j = 0; j < 8; j++) {
                            float w = sfpw[(oblk * 8 + j) * 128 + c];
                            a0[j] += s0 * w;
                            a1[j] += s1 * w;
                        }
                    }
#pragma unroll
                    for (int j = 0; j < 8; j++) {
                        int o = oblk * 8 + j;
                        st3[o * 33 + p0] = fmaxf(a0[j], 0.f);
                        st3[o * 33 + p1] = fmaxf(a1[j], 0.f);
                    }
                }
                __syncthreads();

                // (c) f2 128->32 + residual into sx
                {
                    int pp = tid & 31;
                    int iblk = tid >> 5;       // 0..7, 4 outputs each
                    float acc[4];
#pragma unroll
                    for (int j = 0; j < 4; j++) acc[j] = f2b[iblk * 4 + j];
#pragma unroll 4
                    for (int o = 0; o < 128; o++) {
                        float s = st3[o * 33 + pp];
#pragma unroll
                        for (int j = 0; j < 4; j++)
                            acc[j] += sf2[(iblk * 4 + j) * 128 + o] * s;
                    }
                    int h = h0 + (pp >> 4), w = pp & 15;
#pragma unroll
                    for (int j = 0; j < 4; j++) {
                        int i = iblk * 4 + j;
                        sx[h * 512 + i * 16 + w] += acc[j];
                    }
                }
                __syncthreads();
            }
        }
    } // layers

    __syncthreads();
    // ---- write out ----
    {
        float4* og = (float4*)(p.out + (size_t)b * 8192);
        const float4* sx4 = (const float4*)sx;
#pragma unroll
        for (int it = 0; it < 8; it++) og[tid + NT * it] = sx4[tid + NT * it];
    }
}

extern "C" void kernel_launch(void* const* d_in, const int* in_sizes, int n_in,
                              void* d_out, int out_size) {
    Params p;
    p.x        = (const float*)d_in[0];
    p.ln1_g    = (const float*)d_in[1];
    p.ln1_b    = (const float*)d_in[2];
    p.ln2_g    = (const float*)d_in[3];
    p.ln2_b    = (const float*)d_in[4];
    p.qkv_dw   = (const float*)d_in[5];
    p.qkv_bng  = (const float*)d_in[6];
    p.qkv_bnb  = (const float*)d_in[7];
    p.qkv_bnm  = (const float*)d_in[8];
    p.qkv_bnv  = (const float*)d_in[9];
    p.qkv_pw   = (const float*)d_in[10];
    p.position = (const float*)d_in[11];
    p.c1d_w    = (const float*)d_in[12];
    p.c1d_b    = (const float*)d_in[13];
    p.lin_w    = (const float*)d_in[14];
    p.lin_b    = (const float*)d_in[15];
    p.f1_w     = (const float*)d_in[16];
    p.f1_b     = (const float*)d_in[17];
    p.fdw_w    = (const float*)d_in[18];
    p.fdw_b    = (const float*)d_in[19];
    p.f_bng    = (const float*)d_in[20];
    p.f_bnb    = (const float*)d_in[21];
    p.f_bnm    = (const float*)d_in[22];
    p.f_bnv    = (const float*)d_in[23];
    p.fpw_w    = (const float*)d_in[24];
    p.fpw_b    = (const float*)d_in[25];
    p.f2_w     = (const float*)d_in[26];
    p.f2_b     = (const float*)d_in[27];
    p.out      = (float*)d_out;

    int nb = in_sizes[0] / (16 * 512);   // = 2048

    // idempotent every call; legal during graph capture (not a stream op)
    cudaFuncSetAttribute(encoder_kernel,
                         cudaFuncAttributeMaxDynamicSharedMemorySize, SMEM_BYTES);

    encoder_kernel<<<nb, NT, SMEM_BYTES>>>(p);
}

// round 7
// speedup vs baseline: 1.0493x; 1.0493x over previous
#include <cuda_runtime.h>
#include <cuda_bf16.h>

// ---------------------------------------------------------------------------
// Encoder: B=2048 rows of (16 x 512) fp32 state, 2 layers.
// One CTA per batch row; everything fused in shared memory.
// R6: vectorized (float4) weight loads in all GEMM hot loops; layouts preserved.
// ---------------------------------------------------------------------------

#define NB      2048
#define LAYERS  2
#define DM      512
#define EPSLN   1e-5f
#define NT      256

// ---- shared memory layout (float offsets) ----
#define OFF_SX    0
#define OFF_SXP   8192
#define OFF_STMP  16384
#define OFF_SQ    18432
#define OFF_SK    20512
#define OFF_SV    22592
#define OFF_SO    24672     /* also qkv-pw weight staging (1024 f) */
#define OFF_SO16  26752     /* 16 x 260 -> ends 30912 */
#define OFF_WT    8192      /* lin tile 512 x 36 -> ends 26624 (overlays dead attn bufs) */
#define OFF_ST1   8192      /* bf16 128 x 260 -> ends 24832 */
#define OFF_SXP2  24832
#define OFF_SW1   33024
#define OFF_SFPW  24832     /* loaded after f1, overlays SXP2/SW1 */
#define OFF_ST2   41216
#define OFF_ST3   45568
#define OFF_SF2   49792
#define OFF_SFDW  53888
#define SMEM_FLOATS 55424
#define SMEM_BYTES  (SMEM_FLOATS * 4)

struct Params {
    const float *x;
    const float *ln1_g, *ln1_b, *ln2_g, *ln2_b;
    const float *qkv_dw, *qkv_bng, *qkv_bnb, *qkv_bnm, *qkv_bnv, *qkv_pw;
    const float *position, *c1d_w, *c1d_b, *lin_w, *lin_b;
    const float *f1_w, *f1_b, *fdw_w, *fdw_b;
    const float *f_bng, *f_bnb, *f_bnm, *f_bnv;
    const float *fpw_w, *fpw_b, *f2_w, *f2_b;
    float *out;
};

__device__ __forceinline__ float warp_sum(float v) {
#pragma unroll
    for (int o = 16; o; o >>= 1) v += __shfl_xor_sync(0xffffffffu, v, o);
    return v;
}
__device__ __forceinline__ float warp_max(float v) {
#pragma unroll
    for (int o = 16; o; o >>= 1) v = fmaxf(v, __shfl_xor_sync(0xffffffffu, v, o));
    return v;
}

// LayerNorm of 16x512 rows scattered into patch layout
__device__ __forceinline__ void ln_to_patches(const float* sx, float* dst,
                                              const float* g, const float* bb,
                                              int lane, int wid) {
#pragma unroll
    for (int r = 0; r < 2; r++) {
        int h = wid + 8 * r;
        float s = 0.f, ss = 0.f;
#pragma unroll
        for (int i = 0; i < 16; i++) {
            float v = sx[h * 512 + lane + 32 * i];
            s += v; ss += v * v;
        }
        s = warp_sum(s); ss = warp_sum(ss);
        float mean = s * (1.f / 512.f);
        float var = ss * (1.f / 512.f) - mean * mean;
        float rs = rsqrtf(var + EPSLN);
#pragma unroll
        for (int i = 0; i < 16; i++) {
            int j = lane + 32 * i;
            float v = (sx[h * 512 + j] - mean) * rs * g[j] + bb[j];
            dst[(j >> 4) * 256 + h * 16 + (j & 15)] = v;
        }
    }
}

extern __shared__ float sm[];

__global__ void __launch_bounds__(NT, 1) encoder_kernel(Params p) {
    const int b = blockIdx.x;
    const int tid = threadIdx.x;
    const int lane = tid & 31;
    const int wid = tid >> 5;

    float* sx = sm + OFF_SX;

    // ---- load x (16x512) ----
    {
        const float4* xg = (const float4*)(p.x + (size_t)b * 8192);
        float4* sx4 = (float4*)sx;
#pragma unroll
        for (int it = 0; it < 8; it++) sx4[tid + NT * it] = xg[tid + NT * it];
    }
    __syncthreads();

    for (int l = 0; l < LAYERS; l++) {
        // ================= attention sublayer =================
        ln_to_patches(sx, sm + OFF_SXP, p.ln1_g + l * DM, p.ln1_b + l * DM, lane, wid);
        __syncthreads();

        // ---- q/k/v: depthwise 3x3 s2 + BN + 1x1 pointwise ----
        for (int i = 0; i < 3; i++) {
            const float* sxp = sm + OFF_SXP;
            float* stmp = sm + OFF_STMP;
            float* spw  = sm + OFF_SO;     // staged pw weights (32x32)
            const float* dw  = p.qkv_dw  + (size_t)((l * 3 + i) * 32) * 9;
            const float* bng = p.qkv_bng + (l * 3 + i) * 32;
            const float* bnb = p.qkv_bnb + (l * 3 + i) * 32;
            const float* bnm = p.qkv_bnm + (l * 3 + i) * 32;
            const float* bnv = p.qkv_bnv + (l * 3 + i) * 32;
            // stage pointwise weights (1024 floats, one float4/thread)
            {
                const float4* pwg = (const float4*)(p.qkv_pw + (size_t)((l * 3 + i) * 32) * 32);
                *(float4*)(spw + tid * 4) = pwg[tid];
            }
#pragma unroll 2
            for (int it = 0; it < 8; it++) {
                int u = tid + NT * it;
                int c = u >> 6, pos = u & 63;
                int ch2 = (pos >> 3) * 2, cw2 = (pos & 7) * 2;
                const float* wp = dw + c * 9;
                float acc = 0.f;
#pragma unroll
                for (int kh = 0; kh < 3; kh++) {
                    int ih = ch2 - 1 + kh;
                    if ((unsigned)ih < 16u) {
#pragma unroll
                        for (int kw = 0; kw < 3; kw++) {
                            int iw = cw2 - 1 + kw;
                            if ((unsigned)iw < 16u)
                                acc += sxp[c * 256 + ih * 16 + iw] * wp[kh * 3 + kw];
                        }
                    }
                }
                float sc = bng[c] * rsqrtf(bnv[c] + EPSLN);
                stmp[c * 64 + pos] = acc * sc + (bnb[c] - bnm[c] * sc);
            }
            __syncthreads();
            // pointwise 32->32: thread = (dblk of 8 outs, pos); float4 weights
            {
                float* dstq = sm + OFF_SQ + i * 2080;
                int pos = tid & 63, dblk = tid >> 6;
                float acc[8];
#pragma unroll
                for (int j = 0; j < 8; j++) acc[j] = 0.f;
#pragma unroll
                for (int c = 0; c < 32; c += 4) {
                    float s0 = stmp[(c + 0) * 64 + pos];
                    float s1 = stmp[(c + 1) * 64 + pos];
                    float s2 = stmp[(c + 2) * 64 + pos];
                    float s3 = stmp[(c + 3) * 64 + pos];
#pragma unroll
                    for (int j = 0; j < 8; j++) {
                        float4 w = *(const float4*)(spw + (dblk * 8 + j) * 32 + c);
                        acc[j] += s0 * w.x + s1 * w.y + s2 * w.z + s3 * w.w;
                    }
                }
#pragma unroll
                for (int j = 0; j < 8; j++)
                    dstq[(dblk * 8 + j) * 65 + pos] = acc[j];
            }
            __syncthreads();
        }

        // ---- attention: scores + softmax + weighted V ----
        {
            float* sq = sm + OFF_SQ;
            float* sk = sm + OFF_SK;
            float* sv = sm + OFF_SV;
            float* so = sm + OFF_SO;
            const float* posw = p.position + l * 1024;
#pragma unroll
            for (int r = 0; r < 4; r++) {
                int d = wid + 8 * r;
                const float* qd = sq + d * 65;
                const float* kf = sk + lane * 65;
                float s = 0.f;
#pragma unroll
                for (int e = 0; e < 64; e++) s += qd[e] * kf[e];
                s = s * 0.125f + posw[d * 32 + lane];
                float m = warp_max(s);
                float pe = __expf(s - m);
                float den = warp_sum(pe);
                float pr = pe / den;
                float a0 = 0.f, a1 = 0.f;
#pragma unroll
                for (int f = 0; f < 32; f++) {
                    float pf = __shfl_sync(0xffffffffu, pr, f);
                    a0 += pf * sv[f * 65 + lane];
                    a1 += pf * sv[f * 65 + lane + 32];
                }
                so[d * 65 + lane] = a0;
                so[d * 65 + lane + 32] = a1;
            }
        }
        __syncthreads();

        // ---- c1d: 8 -> 16 ----
        {
            float* so = sm + OFF_SO;
            float* so16 = sm + OFF_SO16;
            int d = tid >> 3, p2 = tid & 7;
            float vals[8];
#pragma unroll
            for (int c = 0; c < 8; c++) vals[c] = so[d * 65 + c * 8 + p2];
            const float* w = p.c1d_w + l * 128;
            const float* bb = p.c1d_b + l * 16;
#pragma unroll
            for (int o = 0; o < 16; o++) {
                float acc = bb[o];
#pragma unroll
                for (int c = 0; c < 8; c++) acc += w[o * 8 + c] * vals[c];
                so16[o * 260 + tid] = acc;
            }
        }
        __syncthreads();

        // ---- lin: out[c16][o512] = sum_d so16[c][d] * lin_w[o][d]; x += out ----
        {
            float* wt = sm + OFF_WT;                 // 512 x 36
            float* so16 = sm + OFF_SO16;             // 16 x 260
            const float* lw = p.lin_w + (size_t)l * 131072;
            float acc[16][2];
#pragma unroll
            for (int c = 0; c < 16; c++) { acc[c][0] = 0.f; acc[c][1] = 0.f; }
            const int oa = tid, ob = tid + 256;
            for (int db = 0; db < 8; db++) {
                int d0 = db * 32;
#pragma unroll
                for (int it = 0; it < 16; it++) {
                    int e4 = tid + NT * it;          // 0..4095
                    int o = e4 >> 3, dd4 = (e4 & 7) * 4;
                    *(float4*)(wt + o * 36 + dd4) = *(const float4*)(lw + o * 256 + d0 + dd4);
                }
                __syncthreads();
#pragma unroll
                for (int dd4 = 0; dd4 < 32; dd4 += 4) {
                    float4 wa = *(const float4*)(wt + oa * 36 + dd4);
                    float4 wb = *(const float4*)(wt + ob * 36 + dd4);
#pragma unroll
                    for (int c = 0; c < 16; c++) {
                        float4 s = *(const float4*)(so16 + c * 260 + d0 + dd4);
                        acc[c][0] += s.x * wa.x + s.y * wa.y + s.z * wa.z + s.w * wa.w;
                        acc[c][1] += s.x * wb.x + s.y * wb.y + s.z * wb.z + s.w * wb.w;
                    }
                }
                __syncthreads();
            }
            const float* lb = p.lin_b + l * 512;
            float ba = lb[oa], bv = lb[ob];
#pragma unroll
            for (int c = 0; c < 16; c++) {
                sx[c * 512 + oa] += acc[c][0] + ba;
                sx[c * 512 + ob] += acc[c][1] + bv;
            }
        }
        __syncthreads();

        // ================= conv-FFN sublayer =================
        ln_to_patches(sx, sm + OFF_SXP2, p.ln2_g + l * DM, p.ln2_b + l * DM, lane, wid);
        {   // preload f1 weights
            float* sw1 = sm + OFF_SW1;
            const float* w = p.f1_w + l * 4096;
#pragma unroll
            for (int it = 0; it < 16; it++) sw1[tid + NT * it] = w[tid + NT * it];
        }
        __syncthreads();

        // ---- f1: 32->128 + ReLU, store bf16 t1[c][pos]; float4 weights ----
        {
            __nv_bfloat16* st1 = (__nv_bfloat16*)(sm + OFF_ST1);
            float* sxp2 = sm + OFF_SXP2;
            float* sw1 = sm + OFF_SW1;
            const float* f1b = p.f1_b + l * 128;
            float sv_[32];
#pragma unroll
            for (int i = 0; i < 32; i++) sv_[i] = sxp2[i * 256 + tid];
            for (int c0 = 0; c0 < 128; c0 += 4) {
                float a[4];
#pragma unroll
                for (int j = 0; j < 4; j++) a[j] = f1b[c0 + j];
#pragma unroll
                for (int i = 0; i < 32; i += 4) {
#pragma unroll
                    for (int j = 0; j < 4; j++) {
                        float4 w = *(const float4*)(sw1 + (c0 + j) * 32 + i);
                        a[j] += sv_[i] * w.x + sv_[i + 1] * w.y +
                                sv_[i + 2] * w.z + sv_[i + 3] * w.w;
                    }
                }
#pragma unroll
                for (int j = 0; j < 4; j++)
                    st1[(c0 + j) * 260 + tid] = __float2bfloat16(fmaxf(a[j], 0.f));
            }
        }
        __syncthreads();

        // ---- load fpw / f2 / folded dw weights ----
        {
            float* sfpw = sm + OFF_SFPW;
            const float* w = p.fpw_w + (size_t)l * 16384;
#pragma unroll
            for (int it = 0; it < 64; it++) sfpw[tid + NT * it] = w[tid + NT * it];
            float* sf2 = sm + OFF_SF2;
            const float* w2 = p.f2_w + l * 4096;
#pragma unroll
            for (int it = 0; it < 16; it++) sf2[tid + NT * it] = w2[tid + NT * it];
            float* sfdw = sm + OFF_SFDW;
            if (tid < 128) {
                int c = tid;
                const float* dwp = p.fdw_w + l * 1152 + c * 9;
#pragma unroll
                for (int k = 0; k < 9; k++) sfdw[c * 12 + k] = dwp[k];
                float sc = p.f_bng[l * 128 + c] * rsqrtf(p.f_bnv[l * 128 + c] + EPSLN);
                sfdw[c * 12 + 9] = sc;
                sfdw[c * 12 + 10] = (p.fdw_b[l * 128 + c] - p.f_bnm[l * 128 + c]) * sc
                                    + p.f_bnb[l * 128 + c];
            }
        }
        __syncthreads();

        // ---- fused dw3x3+BN -> fpw+ReLU -> f2 -> residual, 2 rows at a time ----
        {
            __nv_bfloat16* st1 = (__nv_bfloat16*)(sm + OFF_ST1);
            float* sfpw = sm + OFF_SFPW;
            float* st2 = sm + OFF_ST2;
            float* st3 = sm + OFF_ST3;
            float* sf2 = sm + OFF_SF2;
            float* sfdw = sm + OFF_SFDW;
            const float* fpwb = p.fpw_b + l * 128;
            const float* f2b = p.f2_b + l * 32;

            for (int hb = 0; hb < 8; hb++) {
                int h0 = hb * 2;
                // (a) depthwise 3x3 s1 + BN on rows h0,h0+1 -> st2[c][32]
#pragma unroll 4
                for (int it = 0; it < 16; it++) {
                    int u = tid + NT * it;
                    int c = u >> 5, ppos = u & 31;
                    int rr = ppos >> 4, w = ppos & 15;
                    int h = h0 + rr;
                    const float* fw = sfdw + c * 12;
                    float acc = 0.f;
#pragma unroll
                    for (int kh = 0; kh < 3; kh++) {
                        int ih = h - 1 + kh;
                        if ((unsigned)ih < 16u) {
#pragma unroll
                            for (int kw = 0; kw < 3; kw++) {
                                int iw = w - 1 + kw;
                                if ((unsigned)iw < 16u)
                                    acc += __bfloat162float(st1[c * 260 + ih * 16 + iw])
                                           * fw[kh * 3 + kw];
                            }
                        }
                    }
                    st2[c * 34 + ppos] = acc * fw[9] + fw[10];
                }
                __syncthreads();

                // (b) fpw 128->128 + ReLU -> st3; float4 weights over c
                {
                    int p0 = tid & 15, p1 = p0 + 16;
                    int oblk = tid >> 4;       // 0..15, 8 outputs each
                    float a0[8], a1[8];
#pragma unroll
                    for (int j = 0; j < 8; j++) {
                        float bv = fpwb[oblk * 8 + j];
                        a0[j] = bv; a1[j] = bv;
                    }
#pragma unroll 2
                    for (int c = 0; c < 128; c += 4) {
                        float s00 = st2[(c + 0) * 34 + p0];
                        float s01 = st2[(c + 1) * 34 + p0];
                        float s02 = st2[(c + 2) * 34 + p0];
                        float s03 = st2[(c + 3) * 34 + p0];
                        float s10 = st2[(c + 0) * 34 + p1];
                        float s11 = st2[(c + 1) * 34 + p1];
                        float s12 = st2[(c + 2) * 34 + p1];
                        float s13 = st2[(c + 3) * 34 + p1];
#pragma unroll
                        for (int j = 0; j < 8; j++) {
                            float4 w = *(const float4*)(sfpw + (oblk * 8 + j) * 128 + c);
                            a0[j] += s00 * w.x + s01 * w.y + s02 * w.z + s03 * w.w;
                            a1[j] += s10 * w.x + s11 * w.y + s12 * w.z + s13 * w.w;
                        }
                    }
#pragma unroll
                    for (int j = 0; j < 8; j++) {
                        int o = oblk * 8 + j;
                        st3[o * 33 + p0] = fmaxf(a0[j], 0.f);
                        st3[o * 33 + p1] = fmaxf(a1[j], 0.f);
                    }
                }
                __syncthreads();

                // (c) f2 128->32 + residual into sx; float4 weights over o
                {
                    int pp = tid & 31;
                    int iblk = tid >> 5;       // 0..7, 4 outputs each
                    float acc[4];
#pragma unroll
                    for (int j = 0; j < 4; j++) acc[j] = f2b[iblk * 4 + j];
#pragma unroll 2
                    for (int o = 0; o < 128; o += 4) {
                        float s0 = st3[(o + 0) * 33 + pp];
                        float s1 = st3[(o + 1) * 33 + pp];
                        float s2 = st3[(o + 2) * 33 + pp];
                        float s3 = st3[(o + 3) * 33 + pp];
#pragma unroll
                        for (int j = 0; j < 4; j++) {
                            float4 w = *(const float4*)(sf2 + (iblk * 4 + j) * 128 + o);
                            acc[j] += s0 * w.x + s1 * w.y + s2 * w.z + s3 * w.w;
                        }
                    }
                    int h = h0 + (pp >> 4), w = pp & 15;
#pragma unroll
                    for (int j = 0; j < 4; j++) {
                        int i = iblk * 4 + j;
                        sx[h * 512 + i * 16 + w] += acc[j];
                    }
                }
                __syncthreads();
            }
        }
    } // layers

    __syncthreads();
    // ---- write out ----
    {
        float4* og = (float4*)(p.out + (size_t)b * 8192);
        const float4* sx4 = (const float4*)sx;
#pragma unroll
        for (int it = 0; it < 8; it++) og[tid + NT * it] = sx4[tid + NT * it];
    }
}

extern "C" void kernel_launch(void* const* d_in, const int* in_sizes, int n_in,
                              void* d_out, int out_size) {
    Params p;
    p.x        = (const float*)d_in[0];
    p.ln1_g    = (const float*)d_in[1];
    p.ln1_b    = (const float*)d_in[2];
    p.ln2_g    = (const float*)d_in[3];
    p.ln2_b    = (const float*)d_in[4];
    p.qkv_dw   = (const float*)d_in[5];
    p.qkv_bng  = (const float*)d_in[6];
    p.qkv_bnb  = (const float*)d_in[7];
    p.qkv_bnm  = (const float*)d_in[8];
    p.qkv_bnv  = (const float*)d_in[9];
    p.qkv_pw   = (const float*)d_in[10];
    p.position = (const float*)d_in[11];
    p.c1d_w    = (const float*)d_in[12];
    p.c1d_b    = (const float*)d_in[13];
    p.lin_w    = (const float*)d_in[14];
    p.lin_b    = (const float*)d_in[15];
    p.f1_w     = (const float*)d_in[16];
    p.f1_b     = (const float*)d_in[17];
    p.fdw_w    = (const float*)d_in[18];
    p.fdw_b    = (const float*)d_in[19];
    p.f_bng    = (const float*)d_in[20];
    p.f_bnb    = (const float*)d_in[21];
    p.f_bnm    = (const float*)d_in[22];
    p.f_bnv    = (const float*)d_in[23];
    p.fpw_w    = (const float*)d_in[24];
    p.fpw_b    = (const float*)d_in[25];
    p.f2_w     = (const float*)d_in[26];
    p.f2_b     = (const float*)d_in[27];
    p.out      = (float*)d_out;

    int nb = in_sizes[0] / (16 * 512);   // = 2048

    cudaFuncSetAttribute(encoder_kernel,
                         cudaFuncAttributeMaxDynamicSharedMemorySize, SMEM_BYTES);

    encoder_kernel<<<nb, NT, SMEM_BYTES>>>(p);
}

// round 8
// speedup vs baseline: 2.8530x; 2.7191x over previous
#include <cuda_runtime.h>
#include <cuda_bf16.h>
#include <cstdint>

#define LAYERS 2
#define DM 512
#define EPSLN 1e-5f
#define NT 256

// ---- float offsets (attention scratch, unchanged from passing R6) ----
#define OFF_SX   0
#define OFF_SXP  8192
#define OFF_STMP 16384
#define OFF_SQ   18432
#define OFF_SK   20512
#define OFF_SV   22592
#define OFF_SO   24672
// ---- byte offsets (bf16 MMA buffers) ----
#define BY_XP    32768u   /* xp_bf  [256][40]  20480B  (union w/ fpw weights) */
#define BY_F1W   53248u   /* f1w_bf [128][40]  10240B  (union w/ fpw weights) */
#define BY_FPWW  32768u   /* fpw_bf [128][136] 34816B  (loaded after f1)      */
#define BY_TA    67584u   /* t1 then t3 [256][136] 69632B                      */
#define BY_TB    137216u  /* t2 [256][136]; lin wtb [512][40] during attn      */
#define BY_WTB   137216u
#define BY_F2W   206848u  /* f2w_bf [32][136] 8704B                            */
#define BY_SB1   215552u  /* f32[128] */
#define BY_SBPW  216064u
#define BY_SB2   216576u  /* f32[32] */
#define BY_FDW   216704u  /* f32 128x12 folded dw/BN */
#define BY_SO16B 222848u  /* so16_bf [16][264] 8448B */
#define SMEM_BYTES 231296

// mma.sync m16n8k16 bf16 -> f32
#define MMA_BF16(c0,c1,c2,c3,a0,a1,a2,a3,b0,b1) \
    asm volatile("mma.sync.aligned.m16n8k16.row.col.f32.bf16.bf16.f32 " \
        "{%0,%1,%2,%3}, {%4,%5,%6,%7}, {%8,%9}, {%0,%1,%2,%3};" \
        : "+f"(c0), "+f"(c1), "+f"(c2), "+f"(c3) \
        : "r"(a0), "r"(a1), "r"(a2), "r"(a3), "r"(b0), "r"(b1))

__device__ __forceinline__ uint32_t packbf(float lo, float hi) {
    uint32_t r;
    asm("cvt.rn.bf16x2.f32 %0, %1, %2;" : "=r"(r) : "f"(hi), "f"(lo));
    return r;
}

// A fragment (row-major bf16, stride S elements), 16x16 tile at (row, k)
#define LDA4(A, buf, S, row, k, g, tg)                                          \
    do {                                                                        \
        (A)[0] = *(const uint32_t*)((buf) + ((row)+(g))*(S) + (k) + (tg)*2);    \
        (A)[1] = *(const uint32_t*)((buf) + ((row)+(g)+8)*(S) + (k) + (tg)*2);  \
        (A)[2] = *(const uint32_t*)((buf) + ((row)+(g))*(S) + (k) + 8 + (tg)*2);\
        (A)[3] = *(const uint32_t*)((buf) + ((row)+(g)+8)*(S) + (k) + 8 + (tg)*2);\
    } while (0)

struct Params {
    const float *x;
    const float *ln1_g, *ln1_b, *ln2_g, *ln2_b;
    const float *qkv_dw, *qkv_bng, *qkv_bnb, *qkv_bnm, *qkv_bnv, *qkv_pw;
    const float *position, *c1d_w, *c1d_b, *lin_w, *lin_b;
    const float *f1_w, *f1_b, *fdw_w, *fdw_b;
    const float *f_bng, *f_bnb, *f_bnm, *f_bnv;
    const float *fpw_w, *fpw_b, *f2_w, *f2_b;
    float *out;
};

__device__ __forceinline__ float warp_sum(float v) {
#pragma unroll
    for (int o = 16; o; o >>= 1) v += __shfl_xor_sync(0xffffffffu, v, o);
    return v;
}
__device__ __forceinline__ float warp_max(float v) {
#pragma unroll
    for (int o = 16; o; o >>= 1) v = fmaxf(v, __shfl_xor_sync(0xffffffffu, v, o));
    return v;
}

extern __shared__ float sm[];

__global__ void __launch_bounds__(NT, 1) encoder_kernel(Params p) {
    const int b = blockIdx.x;
    const int tid = threadIdx.x;
    const int lane = tid & 31;
    const int wid = tid >> 5;
    const int g = lane >> 2, tg = lane & 3;
    char* smc = (char*)sm;
    float* sx = sm + OFF_SX;

    // ---- load x (16x512) ----
    {
        const float4* xg = (const float4*)(p.x + (size_t)b * 8192);
        float4* sx4 = (float4*)sx;
#pragma unroll
        for (int it = 0; it < 8; it++) sx4[tid + NT * it] = xg[tid + NT * it];
    }
    __syncthreads();

    for (int l = 0; l < LAYERS; l++) {
        // ================= attention sublayer (scalar, as in R6) =================
        {   // LN1 -> float patches
            const float* gg = p.ln1_g + l * DM; const float* bb = p.ln1_b + l * DM;
            float* dst = sm + OFF_SXP;
#pragma unroll
            for (int r = 0; r < 2; r++) {
                int h = wid + 8 * r;
                float s = 0.f, ss = 0.f;
#pragma unroll
                for (int i = 0; i < 16; i++) {
                    float v = sx[h * 512 + lane + 32 * i];
                    s += v; ss += v * v;
                }
                s = warp_sum(s); ss = warp_sum(ss);
                float mean = s * (1.f / 512.f);
                float rs = rsqrtf(ss * (1.f / 512.f) - mean * mean + EPSLN);
#pragma unroll
                for (int i = 0; i < 16; i++) {
                    int j = lane + 32 * i;
                    float v = (sx[h * 512 + j] - mean) * rs * gg[j] + bb[j];
                    dst[(j >> 4) * 256 + h * 16 + (j & 15)] = v;
                }
            }
        }
        __syncthreads();

        for (int i = 0; i < 3; i++) {   // qkv: dw3x3 s2 + BN + pw
            const float* sxp = sm + OFF_SXP;
            float* stmp = sm + OFF_STMP;
            float* spw  = sm + OFF_SO;
            const float* dw  = p.qkv_dw  + (size_t)((l * 3 + i) * 32) * 9;
            const float* bng = p.qkv_bng + (l * 3 + i) * 32;
            const float* bnb = p.qkv_bnb + (l * 3 + i) * 32;
            const float* bnm = p.qkv_bnm + (l * 3 + i) * 32;
            const float* bnv = p.qkv_bnv + (l * 3 + i) * 32;
            {
                const float4* pwg = (const float4*)(p.qkv_pw + (size_t)((l * 3 + i) * 32) * 32);
                *(float4*)(spw + tid * 4) = pwg[tid];
            }
#pragma unroll 2
            for (int it = 0; it < 8; it++) {
                int u = tid + NT * it;
                int c = u >> 6, pos = u & 63;
                int ch2 = (pos >> 3) * 2, cw2 = (pos & 7) * 2;
                const float* wp = dw + c * 9;
                float acc = 0.f;
#pragma unroll
                for (int kh = 0; kh < 3; kh++) {
                    int ih = ch2 - 1 + kh;
                    if ((unsigned)ih < 16u) {
#pragma unroll
                        for (int kw = 0; kw < 3; kw++) {
                            int iw = cw2 - 1 + kw;
                            if ((unsigned)iw < 16u)
                                acc += sxp[c * 256 + ih * 16 + iw] * wp[kh * 3 + kw];
                        }
                    }
                }
                float sc = bng[c] * rsqrtf(bnv[c] + EPSLN);
                stmp[c * 64 + pos] = acc * sc + (bnb[c] - bnm[c] * sc);
            }
            __syncthreads();
            {
                float* dstq = sm + OFF_SQ + i * 2080;
                int pos = tid & 63, dblk = tid >> 6;
                float acc[8];
#pragma unroll
                for (int j = 0; j < 8; j++) acc[j] = 0.f;
#pragma unroll
                for (int c = 0; c < 32; c += 4) {
                    float s0 = stmp[(c + 0) * 64 + pos];
                    float s1 = stmp[(c + 1) * 64 + pos];
                    float s2 = stmp[(c + 2) * 64 + pos];
                    float s3 = stmp[(c + 3) * 64 + pos];
#pragma unroll
                    for (int j = 0; j < 8; j++) {
                        float4 w = *(const float4*)(spw + (dblk * 8 + j) * 32 + c);
                        acc[j] += s0 * w.x + s1 * w.y + s2 * w.z + s3 * w.w;
                    }
                }
#pragma unroll
                for (int j = 0; j < 8; j++)
                    dstq[(dblk * 8 + j) * 65 + pos] = acc[j];
            }
            __syncthreads();
        }

        {   // attention: scores + softmax + weighted V
            float* sq = sm + OFF_SQ; float* sk = sm + OFF_SK;
            float* sv = sm + OFF_SV; float* so = sm + OFF_SO;
            const float* posw = p.position + l * 1024;
#pragma unroll
            for (int r = 0; r < 4; r++) {
                int d = wid + 8 * r;
                const float* qd = sq + d * 65;
                const float* kf = sk + lane * 65;
                float s = 0.f;
#pragma unroll
                for (int e = 0; e < 64; e++) s += qd[e] * kf[e];
                s = s * 0.125f + posw[d * 32 + lane];
                float m = warp_max(s);
                float pe = __expf(s - m);
                float pr = pe / warp_sum(pe);
                float a0 = 0.f, a1 = 0.f;
#pragma unroll
                for (int f = 0; f < 32; f++) {
                    float pf = __shfl_sync(0xffffffffu, pr, f);
                    a0 += pf * sv[f * 65 + lane];
                    a1 += pf * sv[f * 65 + lane + 32];
                }
                so[d * 65 + lane] = a0;
                so[d * 65 + lane + 32] = a1;
            }
        }
        __syncthreads();

        {   // c1d 8->16, output bf16 [16][264]
            float* so = sm + OFF_SO;
            __nv_bfloat16* so16b = (__nv_bfloat16*)(smc + BY_SO16B);
            int d = tid >> 3, p2 = tid & 7;
            float vals[8];
#pragma unroll
            for (int c = 0; c < 8; c++) vals[c] = so[d * 65 + c * 8 + p2];
            const float* w = p.c1d_w + l * 128;
            const float* bb = p.c1d_b + l * 16;
#pragma unroll
            for (int o = 0; o < 16; o++) {
                float acc = bb[o];
#pragma unroll
                for (int c = 0; c < 8; c++) acc += w[o * 8 + c] * vals[c];
                so16b[o * 264 + tid] = __float2bfloat16(acc);
            }
        }
        __syncthreads();

        // ---- lin via mma: out[16c][512o] = so16[16,256] @ lin_w^T ----
        {
            const float* lw = p.lin_w + (size_t)l * 131072;
            __nv_bfloat16* wtb = (__nv_bfloat16*)(smc + BY_WTB);
            const __nv_bfloat16* so16b = (const __nv_bfloat16*)(smc + BY_SO16B);
            float acc[8][4];
#pragma unroll
            for (int n = 0; n < 8; n++)
#pragma unroll
                for (int q = 0; q < 4; q++) acc[n][q] = 0.f;

            for (int ch = 0; ch < 8; ch++) {
                int d0 = ch * 32;
                // stage bf16 weight chunk [512][32] -> wtb [o][40]
#pragma unroll
                for (int it = 0; it < 16; it++) {
                    int e4 = tid + NT * it;            // 0..4095
                    int o = e4 >> 3, dd4 = (e4 & 7) * 4;
                    float4 v = *(const float4*)(lw + o * 256 + d0 + dd4);
                    *(uint2*)(wtb + o * 40 + dd4) =
                        make_uint2(packbf(v.x, v.y), packbf(v.z, v.w));
                }
                __syncthreads();
                uint32_t A[2][4];
#pragma unroll
                for (int ks = 0; ks < 2; ks++)
                    LDA4(A[ks], so16b, 264, 0, d0 + ks * 16, g, tg);
#pragma unroll
                for (int n = 0; n < 8; n++) {
                    int n0 = (wid * 8 + n) * 8;
#pragma unroll
                    for (int ks = 0; ks < 2; ks++) {
                        int k = ks * 16;
                        uint32_t b0 = *(const uint32_t*)(wtb + (n0 + g) * 40 + k + tg * 2);
                        uint32_t b1 = *(const uint32_t*)(wtb + (n0 + g) * 40 + k + 8 + tg * 2);
                        MMA_BF16(acc[n][0], acc[n][1], acc[n][2], acc[n][3],
                                 A[ks][0], A[ks][1], A[ks][2], A[ks][3], b0, b1);
                    }
                }
                __syncthreads();
            }
            const float* lb = p.lin_b + l * 512;
#pragma unroll
            for (int n = 0; n < 8; n++) {
                int o = (wid * 8 + n) * 8 + tg * 2;
                sx[g * 512 + o]           += acc[n][0] + lb[o];
                sx[g * 512 + o + 1]       += acc[n][1] + lb[o + 1];
                sx[(g + 8) * 512 + o]     += acc[n][2] + lb[o];
                sx[(g + 8) * 512 + o + 1] += acc[n][3] + lb[o + 1];
            }
        }
        __syncthreads();

        // ================= conv-FFN sublayer (mma.sync) =================
        __nv_bfloat16* xpb  = (__nv_bfloat16*)(smc + BY_XP);
        __nv_bfloat16* f1wb = (__nv_bfloat16*)(smc + BY_F1W);
        __nv_bfloat16* t1   = (__nv_bfloat16*)(smc + BY_TA);
        __nv_bfloat16* t2   = (__nv_bfloat16*)(smc + BY_TB);
        __nv_bfloat16* fpwb = (__nv_bfloat16*)(smc + BY_FPWW);
        __nv_bfloat16* t3   = (__nv_bfloat16*)(smc + BY_TA);
        __nv_bfloat16* f2wb = (__nv_bfloat16*)(smc + BY_F2W);
        float* sb1  = (float*)(smc + BY_SB1);
        float* sbpw = (float*)(smc + BY_SBPW);
        float* sb2  = (float*)(smc + BY_SB2);
        float* sfdw = (float*)(smc + BY_FDW);

        {   // LN2 -> xp_bf [pos][40] bf16
            const float* gg = p.ln2_g + l * DM; const float* bb = p.ln2_b + l * DM;
#pragma unroll
            for (int r = 0; r < 2; r++) {
                int h = wid + 8 * r;
                float s = 0.f, ss = 0.f;
#pragma unroll
                for (int i = 0; i < 16; i++) {
                    float v = sx[h * 512 + lane + 32 * i];
                    s += v; ss += v * v;
                }
                s = warp_sum(s); ss = warp_sum(ss);
                float mean = s * (1.f / 512.f);
                float rs = rsqrtf(ss * (1.f / 512.f) - mean * mean + EPSLN);
#pragma unroll
                for (int i = 0; i < 16; i++) {
                    int j = lane + 32 * i;
                    float v = (sx[h * 512 + j] - mean) * rs * gg[j] + bb[j];
                    int d = j >> 4, pp = h * 16 + (j & 15);
                    xpb[pp * 40 + d] = __float2bfloat16(v);
                }
            }
        }
        {   // stage f1w, f2w, biases, folded dw
            const float* w1 = p.f1_w + l * 4096;
#pragma unroll
            for (int it = 0; it < 4; it++) {
                int e4 = tid + NT * it;            // 0..1023
                int n = e4 >> 3, k4 = (e4 & 7) * 4;
                float4 v = *(const float4*)(w1 + n * 32 + k4);
                *(uint2*)(f1wb + n * 40 + k4) =
                    make_uint2(packbf(v.x, v.y), packbf(v.z, v.w));
            }
            const float* w2 = p.f2_w + l * 4096;
#pragma unroll
            for (int it = 0; it < 4; it++) {
                int e4 = tid + NT * it;            // 0..1023
                int i2 = e4 >> 5, o4 = (e4 & 31) * 4;
                float4 v = *(const float4*)(w2 + i2 * 128 + o4);
                *(uint2*)(f2wb + i2 * 136 + o4) =
                    make_uint2(packbf(v.x, v.y), packbf(v.z, v.w));
            }
            if (tid < 128) {
                sb1[tid]  = p.f1_b[l * 128 + tid];
                sbpw[tid] = p.fpw_b[l * 128 + tid];
                float* fw = sfdw + tid * 12;
                const float* dwp = p.fdw_w + l * 1152 + tid * 9;
#pragma unroll
                for (int k = 0; k < 9; k++) fw[k] = dwp[k];
                float sc = p.f_bng[l * 128 + tid] * rsqrtf(p.f_bnv[l * 128 + tid] + EPSLN);
                fw[9] = sc;
                fw[10] = (p.fdw_b[l * 128 + tid] - p.f_bnm[l * 128 + tid]) * sc
                         + p.f_bnb[l * 128 + tid];
            }
            if (tid < 32) sb2[tid] = p.f2_b[l * 32 + tid];
        }
        __syncthreads();

        // ---- f1: [256,128] = xp[256,32] @ f1w^T, +bias, ReLU -> t1 ----
#pragma unroll
        for (int mi = 0; mi < 2; mi++) {
            int row = (wid * 2 + mi) * 16;
            uint32_t A[2][4];
#pragma unroll
            for (int ks = 0; ks < 2; ks++) LDA4(A[ks], xpb, 40, row, ks * 16, g, tg);
#pragma unroll
            for (int n = 0; n < 16; n++) {
                int n0 = n * 8;
                float bias0 = sb1[n0 + tg * 2], bias1 = sb1[n0 + tg * 2 + 1];
                float c0 = bias0, c1 = bias1, c2 = bias0, c3 = bias1;
#pragma unroll
                for (int ks = 0; ks < 2; ks++) {
                    int k = ks * 16;
                    uint32_t b0 = *(const uint32_t*)(f1wb + (n0 + g) * 40 + k + tg * 2);
                    uint32_t b1 = *(const uint32_t*)(f1wb + (n0 + g) * 40 + k + 8 + tg * 2);
                    MMA_BF16(c0, c1, c2, c3, A[ks][0], A[ks][1], A[ks][2], A[ks][3], b0, b1);
                }
                *(uint32_t*)(t1 + (row + g) * 136 + n0 + tg * 2) =
                    packbf(fmaxf(c0, 0.f), fmaxf(c1, 0.f));
                *(uint32_t*)(t1 + (row + g + 8) * 136 + n0 + tg * 2) =
                    packbf(fmaxf(c2, 0.f), fmaxf(c3, 0.f));
            }
        }
        __syncthreads();

        // ---- dw3x3 s1 + BN: t1 -> t2 ; also stage fpw weights ----
        {
#pragma unroll 2
            for (int it = 0; it < 32; it++) {
                int u = it * NT + tid;
                int c = u & 127, pp = u >> 7;
                int w = pp & 15, h0 = (pp >> 4) * 4;
                const float* fw = sfdw + c * 12;
                float vals[6][3];
#pragma unroll
                for (int r = 0; r < 6; r++) {
                    int ih = h0 - 1 + r;
#pragma unroll
                    for (int cc = 0; cc < 3; cc++) {
                        int iw = w - 1 + cc;
                        vals[r][cc] = ((unsigned)ih < 16u && (unsigned)iw < 16u)
                            ? __bfloat162float(t1[(ih * 16 + iw) * 136 + c]) : 0.f;
                    }
                }
#pragma unroll
                for (int j = 0; j < 4; j++) {
                    float a = vals[j][0] * fw[0] + vals[j][1] * fw[1] + vals[j][2] * fw[2]
                            + vals[j+1][0] * fw[3] + vals[j+1][1] * fw[4] + vals[j+1][2] * fw[5]
                            + vals[j+2][0] * fw[6] + vals[j+2][1] * fw[7] + vals[j+2][2] * fw[8];
                    t2[((h0 + j) * 16 + w) * 136 + c] = __float2bfloat16(a * fw[9] + fw[10]);
                }
            }
            // stage fpw weights bf16 [o][136] (overlays dead xp/f1w)
            const float* wpw = p.fpw_w + (size_t)l * 16384;
#pragma unroll
            for (int it = 0; it < 16; it++) {
                int e4 = tid + NT * it;            // 0..4095
                int o = e4 >> 5, c4 = (e4 & 31) * 4;
                float4 v = *(const float4*)(wpw + o * 128 + c4);
                *(uint2*)(fpwb + o * 136 + c4) =
                    make_uint2(packbf(v.x, v.y), packbf(v.z, v.w));
            }
        }
        __syncthreads();

        // ---- fpw: [256,128] = t2[256,128] @ fpw^T, +bias, ReLU -> t3 ----
#pragma unroll
        for (int mi = 0; mi < 2; mi++) {
            int row = (wid * 2 + mi) * 16;
            uint32_t A[8][4];
#pragma unroll
            for (int ks = 0; ks < 8; ks++) LDA4(A[ks], t2, 136, row, ks * 16, g, tg);
#pragma unroll
            for (int n = 0; n < 16; n++) {
                int n0 = n * 8;
                float bias0 = sbpw[n0 + tg * 2], bias1 = sbpw[n0 + tg * 2 + 1];
                float c0 = bias0, c1 = bias1, c2 = bias0, c3 = bias1;
#pragma unroll
                for (int ks = 0; ks < 8; ks++) {
                    int k = ks * 16;
                    uint32_t b0 = *(const uint32_t*)(fpwb + (n0 + g) * 136 + k + tg * 2);
                    uint32_t b1 = *(const uint32_t*)(fpwb + (n0 + g) * 136 + k + 8 + tg * 2);
                    MMA_BF16(c0, c1, c2, c3, A[ks][0], A[ks][1], A[ks][2], A[ks][3], b0, b1);
                }
                *(uint32_t*)(t3 + (row + g) * 136 + n0 + tg * 2) =
                    packbf(fmaxf(c0, 0.f), fmaxf(c1, 0.f));
                *(uint32_t*)(t3 + (row + g + 8) * 136 + n0 + tg * 2) =
                    packbf(fmaxf(c2, 0.f), fmaxf(c3, 0.f));
            }
        }
        __syncthreads();

        // ---- f2: [256,32] = t3[256,128] @ f2w^T, +bias, residual -> sx ----
#pragma unroll
        for (int mi = 0; mi < 2; mi++) {
            int row = (wid * 2 + mi) * 16;
            uint32_t A[8][4];
#pragma unroll
            for (int ks = 0; ks < 8; ks++) LDA4(A[ks], t3, 136, row, ks * 16, g, tg);
#pragma unroll
            for (int n = 0; n < 4; n++) {
                int n0 = n * 8;
                float c0 = 0.f, c1 = 0.f, c2 = 0.f, c3 = 0.f;
#pragma unroll
                for (int ks = 0; ks < 8; ks++) {
                    int k = ks * 16;
                    uint32_t b0 = *(const uint32_t*)(f2wb + (n0 + g) * 136 + k + tg * 2);
                    uint32_t b1 = *(const uint32_t*)(f2wb + (n0 + g) * 136 + k + 8 + tg * 2);
                    MMA_BF16(c0, c1, c2, c3, A[ks][0], A[ks][1], A[ks][2], A[ks][3], b0, b1);
                }
                int i = n0 + tg * 2;
                int pos = row + g, h = pos >> 4, w = pos & 15;
                sx[h * 512 + i * 16 + w]       += c0 + sb2[i];
                sx[h * 512 + (i + 1) * 16 + w] += c1 + sb2[i + 1];
                pos = row + g + 8; h = pos >> 4; w = pos & 15;
                sx[h * 512 + i * 16 + w]       += c2 + sb2[i];
                sx[h * 512 + (i + 1) * 16 + w] += c3 + sb2[i + 1];
            }
        }
        __syncthreads();
    } // layers

    // ---- write out ----
    {
        float4* og = (float4*)(p.out + (size_t)b * 8192);
        const float4* sx4 = (const float4*)sx;
#pragma unroll
        for (int it = 0; it < 8; it++) og[tid + NT * it] = sx4[tid + NT * it];
    }
}

extern "C" void kernel_launch(void* const* d_in, const int* in_sizes, int n_in,
                              void* d_out, int out_size) {
    Params p;
    p.x        = (const float*)d_in[0];
    p.ln1_g    = (const float*)d_in[1];
    p.ln1_b    = (const float*)d_in[2];
    p.ln2_g    = (const float*)d_in[3];
    p.ln2_b    = (const float*)d_in[4];
    p.qkv_dw   = (const float*)d_in[5];
    p.qkv_bng  = (const float*)d_in[6];
    p.qkv_bnb  = (const float*)d_in[7];
    p.qkv_bnm  = (const float*)d_in[8];
    p.qkv_bnv  = (const float*)d_in[9];
    p.qkv_pw   = (const float*)d_in[10];
    p.position = (const float*)d_in[11];
    p.c1d_w    = (const float*)d_in[12];
    p.c1d_b    = (const float*)d_in[13];
    p.lin_w    = (const float*)d_in[14];
    p.lin_b    = (const float*)d_in[15];
    p.f1_w     = (const float*)d_in[16];
    p.f1_b     = (const float*)d_in[17];
    p.fdw_w    = (const float*)d_in[18];
    p.fdw_b    = (const float*)d_in[19];
    p.f_bng    = (const float*)d_in[20];
    p.f_bnb    = (const float*)d_in[21];
    p.f_bnm    = (const float*)d_in[22];
    p.f_bnv    = (const float*)d_in[23];
    p.fpw_w    = (const float*)d_in[24];
    p.fpw_b    = (const float*)d_in[25];
    p.f2_w     = (const float*)d_in[26];
    p.f2_b     = (const float*)d_in[27];
    p.out      = (float*)d_out;

    int nb = in_sizes[0] / (16 * 512);   // 2048

    cudaFuncSetAttribute(encoder_kernel,
                         cudaFuncAttributeMaxDynamicSharedMemorySize, SMEM_BYTES);
    encoder_kernel<<<nb, NT, SMEM_BYTES>>>(p);
}

// round 9
// speedup vs baseline: 3.5366x; 1.2396x over previous
#include <cuda_runtime.h>
#include <cuda_bf16.h>
#include <cstdint>

#define LAYERS 2
#define DM 512
#define EPSLN 1e-5f
#define NT 256

// ---- byte offsets ----
// attention phase:
#define BY_SXP   32768u   /* f32 patches [32][256] 32KB -> 65536 */
#define BY_STMP  65536u   /* f32 [32][64] 8KB -> 73728 */
#define BY_QB    73728u   /* bf16 [32][72] 4608B */
#define BY_KB    78336u   /* bf16 [32][72] 4608B */
#define BY_VB    82944u   /* bf16 [64][72] 9216B -> 92160 */
#define BY_SOF   92160u   /* f32 so [32][65] 8320B -> 100480 */
#define BY_SPW   100480u  /* f32 qkv pw weights [32][32] 4096B -> 104576 */
// FFN phase (same as R7):
#define BY_XP    32768u   /* xp_bf [256][40] */
#define BY_F1W   53248u   /* f1w_bf [128][40] */
#define BY_FPWW  32768u   /* fpw_bf [128][136] (after f1) */
#define BY_TA    67584u   /* t1 / t3 [256][136] */
#define BY_TB    137216u  /* t2 [256][136]; lin wtb during attn */
#define BY_WTB   137216u
#define BY_F2W   206848u
#define BY_SB1   215552u
#define BY_SBPW  216064u
#define BY_SB2   216576u
#define BY_FDW   216704u
#define BY_SO16B 222848u
#define SMEM_BYTES 231296

#define MMA_BF16(c0,c1,c2,c3,a0,a1,a2,a3,b0,b1) \
    asm volatile("mma.sync.aligned.m16n8k16.row.col.f32.bf16.bf16.f32 " \
        "{%0,%1,%2,%3}, {%4,%5,%6,%7}, {%8,%9}, {%0,%1,%2,%3};" \
        : "+f"(c0), "+f"(c1), "+f"(c2), "+f"(c3) \
        : "r"(a0), "r"(a1), "r"(a2), "r"(a3), "r"(b0), "r"(b1))

__device__ __forceinline__ uint32_t packbf(float lo, float hi) {
    uint32_t r;
    asm("cvt.rn.bf16x2.f32 %0, %1, %2;" : "=r"(r) : "f"(hi), "f"(lo));
    return r;
}

#define LDA4(A, buf, S, row, k, g, tg)                                          \
    do {                                                                        \
        (A)[0] = *(const uint32_t*)((buf) + ((row)+(g))*(S) + (k) + (tg)*2);    \
        (A)[1] = *(const uint32_t*)((buf) + ((row)+(g)+8)*(S) + (k) + (tg)*2);  \
        (A)[2] = *(const uint32_t*)((buf) + ((row)+(g))*(S) + (k) + 8 + (tg)*2);\
        (A)[3] = *(const uint32_t*)((buf) + ((row)+(g)+8)*(S) + (k) + 8 + (tg)*2);\
    } while (0)

struct Params {
    const float *x;
    const float *ln1_g, *ln1_b, *ln2_g, *ln2_b;
    const float *qkv_dw, *qkv_bng, *qkv_bnb, *qkv_bnm, *qkv_bnv, *qkv_pw;
    const float *position, *c1d_w, *c1d_b, *lin_w, *lin_b;
    const float *f1_w, *f1_b, *fdw_w, *fdw_b;
    const float *f_bng, *f_bnb, *f_bnm, *f_bnv;
    const float *fpw_w, *fpw_b, *f2_w, *f2_b;
    float *out;
};

__device__ __forceinline__ float warp_sum(float v) {
#pragma unroll
    for (int o = 16; o; o >>= 1) v += __shfl_xor_sync(0xffffffffu, v, o);
    return v;
}

extern __shared__ float sm[];

__global__ void __launch_bounds__(NT, 1) encoder_kernel(Params p) {
    const int b = blockIdx.x;
    const int tid = threadIdx.x;
    const int lane = tid & 31;
    const int wid = tid >> 5;
    const int g = lane >> 2, tg = lane & 3;
    char* smc = (char*)sm;
    float* sx = sm;

    // ---- load x (16x512) ----
    {
        const float4* xg = (const float4*)(p.x + (size_t)b * 8192);
        float4* sx4 = (float4*)sx;
#pragma unroll
        for (int it = 0; it < 8; it++) sx4[tid + NT * it] = xg[tid + NT * it];
    }
    __syncthreads();

    for (int l = 0; l < LAYERS; l++) {
        float* sxp  = (float*)(smc + BY_SXP);
        float* stmp = (float*)(smc + BY_STMP);
        __nv_bfloat16* qb = (__nv_bfloat16*)(smc + BY_QB);
        __nv_bfloat16* kb = (__nv_bfloat16*)(smc + BY_KB);
        __nv_bfloat16* vb = (__nv_bfloat16*)(smc + BY_VB);
        float* so   = (float*)(smc + BY_SOF);
        float* spw  = (float*)(smc + BY_SPW);

        // ---- LN1 -> f32 patches ----
        {
            const float* gg = p.ln1_g + l * DM; const float* bb = p.ln1_b + l * DM;
#pragma unroll
            for (int r = 0; r < 2; r++) {
                int h = wid + 8 * r;
                float s = 0.f, ss = 0.f;
#pragma unroll
                for (int i = 0; i < 16; i++) {
                    float v = sx[h * 512 + lane + 32 * i];
                    s += v; ss += v * v;
                }
                s = warp_sum(s); ss = warp_sum(ss);
                float mean = s * (1.f / 512.f);
                float rs = rsqrtf(ss * (1.f / 512.f) - mean * mean + EPSLN);
#pragma unroll
                for (int i = 0; i < 16; i++) {
                    int j = lane + 32 * i;
                    float v = (sx[h * 512 + j] - mean) * rs * gg[j] + bb[j];
                    sxp[(j >> 4) * 256 + h * 16 + (j & 15)] = v;
                }
            }
        }
        __syncthreads();

        // ---- q/k/v: dw3x3 s2 + BN + pw (pw output -> bf16 mma buffers) ----
        for (int i = 0; i < 3; i++) {
            const float* dw  = p.qkv_dw  + (size_t)((l * 3 + i) * 32) * 9;
            const float* bng = p.qkv_bng + (l * 3 + i) * 32;
            const float* bnb = p.qkv_bnb + (l * 3 + i) * 32;
            const float* bnm = p.qkv_bnm + (l * 3 + i) * 32;
            const float* bnv = p.qkv_bnv + (l * 3 + i) * 32;
            {
                const float4* pwg = (const float4*)(p.qkv_pw + (size_t)((l * 3 + i) * 32) * 32);
                *(float4*)(spw + tid * 4) = pwg[tid];
            }
#pragma unroll 2
            for (int it = 0; it < 8; it++) {
                int u = tid + NT * it;
                int c = u >> 6, pos = u & 63;
                int ch2 = (pos >> 3) * 2, cw2 = (pos & 7) * 2;
                const float* wp = dw + c * 9;
                float acc = 0.f;
#pragma unroll
                for (int kh = 0; kh < 3; kh++) {
                    int ih = ch2 - 1 + kh;
                    if ((unsigned)ih < 16u) {
#pragma unroll
                        for (int kw = 0; kw < 3; kw++) {
                            int iw = cw2 - 1 + kw;
                            if ((unsigned)iw < 16u)
                                acc += sxp[c * 256 + ih * 16 + iw] * wp[kh * 3 + kw];
                        }
                    }
                }
                float sc = bng[c] * rsqrtf(bnv[c] + EPSLN);
                stmp[c * 64 + pos] = acc * sc + (bnb[c] - bnm[c] * sc);
            }
            __syncthreads();
            {   // pw 32->32, bf16 out
                int pos = tid & 63, dblk = tid >> 6;
                float acc[8];
#pragma unroll
                for (int j = 0; j < 8; j++) acc[j] = 0.f;
#pragma unroll
                for (int c = 0; c < 32; c += 4) {
                    float s0 = stmp[(c + 0) * 64 + pos];
                    float s1 = stmp[(c + 1) * 64 + pos];
                    float s2 = stmp[(c + 2) * 64 + pos];
                    float s3 = stmp[(c + 3) * 64 + pos];
#pragma unroll
                    for (int j = 0; j < 8; j++) {
                        float4 w = *(const float4*)(spw + (dblk * 8 + j) * 32 + c);
                        acc[j] += s0 * w.x + s1 * w.y + s2 * w.z + s3 * w.w;
                    }
                }
                if (i < 2) {
                    __nv_bfloat16* dst = (i == 0) ? qb : kb;
#pragma unroll
                    for (int j = 0; j < 8; j++)
                        dst[(dblk * 8 + j) * 72 + pos] = __float2bfloat16(acc[j]);
                } else {   // v transposed: [pos][feature]
#pragma unroll
                    for (int jj = 0; jj < 4; jj++)
                        *(uint32_t*)(vb + pos * 72 + dblk * 8 + jj * 2) =
                            packbf(acc[2 * jj], acc[2 * jj + 1]);
                }
            }
            __syncthreads();
        }

        // ---- attention via mma (warps 0,1) ----
        if (wid < 2) {
            const float* posw = p.position + l * 1024;
            int m0 = wid * 16;
            uint32_t Aq[4][4];
#pragma unroll
            for (int kt = 0; kt < 4; kt++) LDA4(Aq[kt], qb, 72, m0, kt * 16, g, tg);
            float c[4][4];
#pragma unroll
            for (int nt = 0; nt < 4; nt++) {
                c[nt][0] = c[nt][1] = c[nt][2] = c[nt][3] = 0.f;
#pragma unroll
                for (int kt = 0; kt < 4; kt++) {
                    uint32_t b0 = *(const uint32_t*)(kb + (nt * 8 + g) * 72 + kt * 16 + tg * 2);
                    uint32_t b1 = *(const uint32_t*)(kb + (nt * 8 + g) * 72 + kt * 16 + 8 + tg * 2);
                    MMA_BF16(c[nt][0], c[nt][1], c[nt][2], c[nt][3],
                             Aq[kt][0], Aq[kt][1], Aq[kt][2], Aq[kt][3], b0, b1);
                }
            }
            // scale + position bias
#pragma unroll
            for (int nt = 0; nt < 4; nt++) {
                int col = nt * 8 + tg * 2;
                c[nt][0] = c[nt][0] * 0.125f + posw[(m0 + g) * 32 + col];
                c[nt][1] = c[nt][1] * 0.125f + posw[(m0 + g) * 32 + col + 1];
                c[nt][2] = c[nt][2] * 0.125f + posw[(m0 + g + 8) * 32 + col];
                c[nt][3] = c[nt][3] * 0.125f + posw[(m0 + g + 8) * 32 + col + 1];
            }
            // softmax: row (m0+g) in c[*][0..1], row (m0+g+8) in c[*][2..3]
            float mx0 = -1e30f, mx1 = -1e30f;
#pragma unroll
            for (int nt = 0; nt < 4; nt++) {
                mx0 = fmaxf(mx0, fmaxf(c[nt][0], c[nt][1]));
                mx1 = fmaxf(mx1, fmaxf(c[nt][2], c[nt][3]));
            }
#pragma unroll
            for (int o = 1; o <= 2; o <<= 1) {
                mx0 = fmaxf(mx0, __shfl_xor_sync(0xffffffffu, mx0, o));
                mx1 = fmaxf(mx1, __shfl_xor_sync(0xffffffffu, mx1, o));
            }
            float sm0 = 0.f, sm1 = 0.f;
#pragma unroll
            for (int nt = 0; nt < 4; nt++) {
                c[nt][0] = __expf(c[nt][0] - mx0); sm0 += c[nt][0];
                c[nt][1] = __expf(c[nt][1] - mx0); sm0 += c[nt][1];
                c[nt][2] = __expf(c[nt][2] - mx1); sm1 += c[nt][2];
                c[nt][3] = __expf(c[nt][3] - mx1); sm1 += c[nt][3];
            }
#pragma unroll
            for (int o = 1; o <= 2; o <<= 1) {
                sm0 += __shfl_xor_sync(0xffffffffu, sm0, o);
                sm1 += __shfl_xor_sync(0xffffffffu, sm1, o);
            }
            float i0 = 1.f / sm0, i1 = 1.f / sm1;
#pragma unroll
            for (int nt = 0; nt < 4; nt++) {
                c[nt][0] *= i0; c[nt][1] *= i0; c[nt][2] *= i1; c[nt][3] *= i1;
            }
            // repack P into A-fragments (C-frag layout == A-frag layout)
            uint32_t Ap[2][4];
#pragma unroll
            for (int kt2 = 0; kt2 < 2; kt2++) {
                Ap[kt2][0] = packbf(c[2 * kt2][0], c[2 * kt2][1]);
                Ap[kt2][1] = packbf(c[2 * kt2][2], c[2 * kt2][3]);
                Ap[kt2][2] = packbf(c[2 * kt2 + 1][0], c[2 * kt2 + 1][1]);
                Ap[kt2][3] = packbf(c[2 * kt2 + 1][2], c[2 * kt2 + 1][3]);
            }
            // AV: o[16,64] = P[16,32] @ V(vb=[e][f])^T
#pragma unroll
            for (int nt = 0; nt < 8; nt++) {
                float o0 = 0.f, o1 = 0.f, o2 = 0.f, o3 = 0.f;
#pragma unroll
                for (int kt2 = 0; kt2 < 2; kt2++) {
                    uint32_t b0 = *(const uint32_t*)(vb + (nt * 8 + g) * 72 + kt2 * 16 + tg * 2);
                    uint32_t b1 = *(const uint32_t*)(vb + (nt * 8 + g) * 72 + kt2 * 16 + 8 + tg * 2);
                    MMA_BF16(o0, o1, o2, o3, Ap[kt2][0], Ap[kt2][1], Ap[kt2][2], Ap[kt2][3], b0, b1);
                }
                int colE = nt * 8 + tg * 2;
                so[(m0 + g) * 65 + colE]     = o0;
                so[(m0 + g) * 65 + colE + 1] = o1;
                so[(m0 + g + 8) * 65 + colE]     = o2;
                so[(m0 + g + 8) * 65 + colE + 1] = o3;
            }
        }
        __syncthreads();

        // ---- c1d 8->16, output bf16 [16][264] ----
        {
            __nv_bfloat16* so16b = (__nv_bfloat16*)(smc + BY_SO16B);
            int d = tid >> 3, p2 = tid & 7;
            float vals[8];
#pragma unroll
            for (int c = 0; c < 8; c++) vals[c] = so[d * 65 + c * 8 + p2];
            const float* w = p.c1d_w + l * 128;
            const float* bb = p.c1d_b + l * 16;
#pragma unroll
            for (int o = 0; o < 16; o++) {
                float acc = bb[o];
#pragma unroll
                for (int c = 0; c < 8; c++) acc += w[o * 8 + c] * vals[c];
                so16b[o * 264 + tid] = __float2bfloat16(acc);
            }
        }
        __syncthreads();

        // ---- lin via mma: out[16c][512o] ----
        {
            const float* lw = p.lin_w + (size_t)l * 131072;
            __nv_bfloat16* wtb = (__nv_bfloat16*)(smc + BY_WTB);
            const __nv_bfloat16* so16b = (const __nv_bfloat16*)(smc + BY_SO16B);
            float acc[8][4];
#pragma unroll
            for (int n = 0; n < 8; n++)
#pragma unroll
                for (int q = 0; q < 4; q++) acc[n][q] = 0.f;

            for (int ch = 0; ch < 8; ch++) {
                int d0 = ch * 32;
#pragma unroll
                for (int it = 0; it < 16; it++) {
                    int e4 = tid + NT * it;
                    int o = e4 >> 3, dd4 = (e4 & 7) * 4;
                    float4 v = *(const float4*)(lw + o * 256 + d0 + dd4);
                    *(uint2*)(wtb + o * 40 + dd4) =
                        make_uint2(packbf(v.x, v.y), packbf(v.z, v.w));
                }
                __syncthreads();
                uint32_t A[2][4];
#pragma unroll
                for (int ks = 0; ks < 2; ks++)
                    LDA4(A[ks], so16b, 264, 0, d0 + ks * 16, g, tg);
#pragma unroll
                for (int n = 0; n < 8; n++) {
                    int n0 = (wid * 8 + n) * 8;
#pragma unroll
                    for (int ks = 0; ks < 2; ks++) {
                        int k = ks * 16;
                        uint32_t b0 = *(const uint32_t*)(wtb + (n0 + g) * 40 + k + tg * 2);
                        uint32_t b1 = *(const uint32_t*)(wtb + (n0 + g) * 40 + k + 8 + tg * 2);
                        MMA_BF16(acc[n][0], acc[n][1], acc[n][2], acc[n][3],
                                 A[ks][0], A[ks][1], A[ks][2], A[ks][3], b0, b1);
                    }
                }
                __syncthreads();
            }
            const float* lb = p.lin_b + l * 512;
#pragma unroll
            for (int n = 0; n < 8; n++) {
                int o = (wid * 8 + n) * 8 + tg * 2;
                sx[g * 512 + o]           += acc[n][0] + lb[o];
                sx[g * 512 + o + 1]       += acc[n][1] + lb[o + 1];
                sx[(g + 8) * 512 + o]     += acc[n][2] + lb[o];
                sx[(g + 8) * 512 + o + 1] += acc[n][3] + lb[o + 1];
            }
        }
        __syncthreads();

        // ================= conv-FFN sublayer =================
        __nv_bfloat16* xpb  = (__nv_bfloat16*)(smc + BY_XP);
        __nv_bfloat16* f1wb = (__nv_bfloat16*)(smc + BY_F1W);
        __nv_bfloat16* t1   = (__nv_bfloat16*)(smc + BY_TA);
        __nv_bfloat16* t2   = (__nv_bfloat16*)(smc + BY_TB);
        __nv_bfloat16* fpwb = (__nv_bfloat16*)(smc + BY_FPWW);
        __nv_bfloat16* t3   = (__nv_bfloat16*)(smc + BY_TA);
        __nv_bfloat16* f2wb = (__nv_bfloat16*)(smc + BY_F2W);
        float* sb1  = (float*)(smc + BY_SB1);
        float* sbpw = (float*)(smc + BY_SBPW);
        float* sb2  = (float*)(smc + BY_SB2);
        float* sfdw = (float*)(smc + BY_FDW);

        {   // LN2 -> xp_bf [pos][40]
            const float* gg = p.ln2_g + l * DM; const float* bb = p.ln2_b + l * DM;
#pragma unroll
            for (int r = 0; r < 2; r++) {
                int h = wid + 8 * r;
                float s = 0.f, ss = 0.f;
#pragma unroll
                for (int i = 0; i < 16; i++) {
                    float v = sx[h * 512 + lane + 32 * i];
                    s += v; ss += v * v;
                }
                s = warp_sum(s); ss = warp_sum(ss);
                float mean = s * (1.f / 512.f);
                float rs = rsqrtf(ss * (1.f / 512.f) - mean * mean + EPSLN);
#pragma unroll
                for (int i = 0; i < 16; i++) {
                    int j = lane + 32 * i;
                    float v = (sx[h * 512 + j] - mean) * rs * gg[j] + bb[j];
                    int d = j >> 4, pp = h * 16 + (j & 15);
                    xpb[pp * 40 + d] = __float2bfloat16(v);
                }
            }
        }
        {   // stage f1w, f2w, biases, folded dw
            const float* w1 = p.f1_w + l * 4096;
#pragma unroll
            for (int it = 0; it < 4; it++) {
                int e4 = tid + NT * it;
                int n = e4 >> 3, k4 = (e4 & 7) * 4;
                float4 v = *(const float4*)(w1 + n * 32 + k4);
                *(uint2*)(f1wb + n * 40 + k4) =
                    make_uint2(packbf(v.x, v.y), packbf(v.z, v.w));
            }
            const float* w2 = p.f2_w + l * 4096;
#pragma unroll
            for (int it = 0; it < 4; it++) {
                int e4 = tid + NT * it;
                int i2 = e4 >> 5, o4 = (e4 & 31) * 4;
                float4 v = *(const float4*)(w2 + i2 * 128 + o4);
                *(uint2*)(f2wb + i2 * 136 + o4) =
                    make_uint2(packbf(v.x, v.y), packbf(v.z, v.w));
            }
            if (tid < 128) {
                sb1[tid]  = p.f1_b[l * 128 + tid];
                sbpw[tid] = p.fpw_b[l * 128 + tid];
                float* fw = sfdw + tid * 12;
                const float* dwp = p.fdw_w + l * 1152 + tid * 9;
#pragma unroll
                for (int k = 0; k < 9; k++) fw[k] = dwp[k];
                float sc = p.f_bng[l * 128 + tid] * rsqrtf(p.f_bnv[l * 128 + tid] + EPSLN);
                fw[9] = sc;
                fw[10] = (p.fdw_b[l * 128 + tid] - p.f_bnm[l * 128 + tid]) * sc
                         + p.f_bnb[l * 128 + tid];
            }
            if (tid < 32) sb2[tid] = p.f2_b[l * 32 + tid];
        }
        __syncthreads();

        // ---- f1: [256,128] = xp @ f1w^T, +bias, ReLU -> t1 ----
#pragma unroll
        for (int mi = 0; mi < 2; mi++) {
            int row = (wid * 2 + mi) * 16;
            uint32_t A[2][4];
#pragma unroll
            for (int ks = 0; ks < 2; ks++) LDA4(A[ks], xpb, 40, row, ks * 16, g, tg);
#pragma unroll
            for (int n = 0; n < 16; n++) {
                int n0 = n * 8;
                float bias0 = sb1[n0 + tg * 2], bias1 = sb1[n0 + tg * 2 + 1];
                float c0 = bias0, c1 = bias1, c2 = bias0, c3 = bias1;
#pragma unroll
                for (int ks = 0; ks < 2; ks++) {
                    int k = ks * 16;
                    uint32_t b0 = *(const uint32_t*)(f1wb + (n0 + g) * 40 + k + tg * 2);
                    uint32_t b1 = *(const uint32_t*)(f1wb + (n0 + g) * 40 + k + 8 + tg * 2);
                    MMA_BF16(c0, c1, c2, c3, A[ks][0], A[ks][1], A[ks][2], A[ks][3], b0, b1);
                }
                *(uint32_t*)(t1 + (row + g) * 136 + n0 + tg * 2) =
                    packbf(fmaxf(c0, 0.f), fmaxf(c1, 0.f));
                *(uint32_t*)(t1 + (row + g + 8) * 136 + n0 + tg * 2) =
                    packbf(fmaxf(c2, 0.f), fmaxf(c3, 0.f));
            }
        }
        __syncthreads();

        // ---- dw3x3 s1 + BN (rolling window, channel pairs) -> t2 ----
        {
            int cp = tid & 63;          // channel pair: c = 2cp, 2cp+1
            int wq = tid >> 6;          // w quad
            int w0 = wq * 4;
            int c0 = cp * 2;
            const float* fwa = sfdw + c0 * 12;
            const float* fwb = sfdw + (c0 + 1) * 12;
            float2 kc[9];
#pragma unroll
            for (int t = 0; t < 9; t++) kc[t] = make_float2(fwa[t], fwb[t]);
            float2 scl = make_float2(fwa[9], fwb[9]);
            float2 shf = make_float2(fwa[10], fwb[10]);

            float2 rA[6], rB[6], rC[6];
#pragma unroll
            for (int i = 0; i < 6; i++) {
                rA[i] = make_float2(0.f, 0.f);
                int iw = w0 - 1 + i;
                rB[i] = ((unsigned)iw < 16u)
                    ? __bfloat1622float2(*(const __nv_bfloat162*)(t1 + iw * 136 + c0))
                    : make_float2(0.f, 0.f);
            }
#pragma unroll
            for (int h = 0; h < 16; h++) {
                if (h < 15) {
#pragma unroll
                    for (int i = 0; i < 6; i++) {
                        int iw = w0 - 1 + i;
                        rC[i] = ((unsigned)iw < 16u)
                            ? __bfloat1622float2(*(const __nv_bfloat162*)(t1 + ((h + 1) * 16 + iw) * 136 + c0))
                            : make_float2(0.f, 0.f);
                    }
                } else {
#pragma unroll
                    for (int i = 0; i < 6; i++) rC[i] = make_float2(0.f, 0.f);
                }
#pragma unroll
                for (int j = 0; j < 4; j++) {
                    float ax = rA[j].x * kc[0].x + rA[j+1].x * kc[1].x + rA[j+2].x * kc[2].x
                             + rB[j].x * kc[3].x + rB[j+1].x * kc[4].x + rB[j+2].x * kc[5].x
                             + rC[j].x * kc[6].x + rC[j+1].x * kc[7].x + rC[j+2].x * kc[8].x;
                    float ay = rA[j].y * kc[0].y + rA[j+1].y * kc[1].y + rA[j+2].y * kc[2].y
                             + rB[j].y * kc[3].y + rB[j+1].y * kc[4].y + rB[j+2].y * kc[5].y
                             + rC[j].y * kc[6].y + rC[j+1].y * kc[7].y + rC[j+2].y * kc[8].y;
                    *(uint32_t*)(t2 + (h * 16 + w0 + j) * 136 + c0) =
                        packbf(ax * scl.x + shf.x, ay * scl.y + shf.y);
                }
#pragma unroll
                for (int i = 0; i < 6; i++) { rA[i] = rB[i]; rB[i] = rC[i]; }
            }
            // stage fpw weights (overlays dead xp/f1w)
            const float* wpw = p.fpw_w + (size_t)l * 16384;
#pragma unroll
            for (int it = 0; it < 16; it++) {
                int e4 = tid + NT * it;
                int o = e4 >> 5, c4 = (e4 & 31) * 4;
                float4 v = *(const float4*)(wpw + o * 128 + c4);
                *(uint2*)(fpwb + o * 136 + c4) =
                    make_uint2(packbf(v.x, v.y), packbf(v.z, v.w));
            }
        }
        __syncthreads();

        // ---- fpw: [256,128] = t2 @ fpw^T, +bias, ReLU -> t3 ----
#pragma unroll
        for (int mi = 0; mi < 2; mi++) {
            int row = (wid * 2 + mi) * 16;
            uint32_t A[8][4];
#pragma unroll
            for (int ks = 0; ks < 8; ks++) LDA4(A[ks], t2, 136, row, ks * 16, g, tg);
#pragma unroll
            for (int n = 0; n < 16; n++) {
                int n0 = n * 8;
                float bias0 = sbpw[n0 + tg * 2], bias1 = sbpw[n0 + tg * 2 + 1];
                float c0 = bias0, c1 = bias1, c2 = bias0, c3 = bias1;
#pragma unroll
                for (int ks = 0; ks < 8; ks++) {
                    int k = ks * 16;
                    uint32_t b0 = *(const uint32_t*)(fpwb + (n0 + g) * 136 + k + tg * 2);
                    uint32_t b1 = *(const uint32_t*)(fpwb + (n0 + g) * 136 + k + 8 + tg * 2);
                    MMA_BF16(c0, c1, c2, c3, A[ks][0], A[ks][1], A[ks][2], A[ks][3], b0, b1);
                }
                *(uint32_t*)(t3 + (row + g) * 136 + n0 + tg * 2) =
                    packbf(fmaxf(c0, 0.f), fmaxf(c1, 0.f));
                *(uint32_t*)(t3 + (row + g + 8) * 136 + n0 + tg * 2) =
                    packbf(fmaxf(c2, 0.f), fmaxf(c3, 0.f));
            }
        }
        __syncthreads();

        // ---- f2: [256,32] = t3 @ f2w^T, +bias, residual -> sx ----
#pragma unroll
        for (int mi = 0; mi < 2; mi++) {
            int row = (wid * 2 + mi) * 16;
            uint32_t A[8][4];
#pragma unroll
            for (int ks = 0; ks < 8; ks++) LDA4(A[ks], t3, 136, row, ks * 16, g, tg);
#pragma unroll
            for (int n = 0; n < 4; n++) {
                int n0 = n * 8;
                float c0 = 0.f, c1 = 0.f, c2 = 0.f, c3 = 0.f;
#pragma unroll
                for (int ks = 0; ks < 8; ks++) {
                    int k = ks * 16;
                    uint32_t b0 = *(const uint32_t*)(f2wb + (n0 + g) * 136 + k + tg * 2);
                    uint32_t b1 = *(const uint32_t*)(f2wb + (n0 + g) * 136 + k + 8 + tg * 2);
                    MMA_BF16(c0, c1, c2, c3, A[ks][0], A[ks][1], A[ks][2], A[ks][3], b0, b1);
                }
                int i = n0 + tg * 2;
                int pos = row + g, h = pos >> 4, w = pos & 15;
                sx[h * 512 + i * 16 + w]       += c0 + sb2[i];
                sx[h * 512 + (i + 1) * 16 + w] += c1 + sb2[i + 1];
                pos = row + g + 8; h = pos >> 4; w = pos & 15;
                sx[h * 512 + i * 16 + w]       += c2 + sb2[i];
                sx[h * 512 + (i + 1) * 16 + w] += c3 + sb2[i + 1];
            }
        }
        __syncthreads();
    } // layers

    // ---- write out ----
    {
        float4* og = (float4*)(p.out + (size_t)b * 8192);
        const float4* sx4 = (const float4*)sx;
#pragma unroll
        for (int it = 0; it < 8; it++) og[tid + NT * it] = sx4[tid + NT * it];
    }
}

extern "C" void kernel_launch(void* const* d_in, const int* in_sizes, int n_in,
                              void* d_out, int out_size) {
    Params p;
    p.x        = (const float*)d_in[0];
    p.ln1_g    = (const float*)d_in[1];
    p.ln1_b    = (const float*)d_in[2];
    p.ln2_g    = (const float*)d_in[3];
    p.ln2_b    = (const float*)d_in[4];
    p.qkv_dw   = (const float*)d_in[5];
    p.qkv_bng  = (const float*)d_in[6];
    p.qkv_bnb  = (const float*)d_in[7];
    p.qkv_bnm  = (const float*)d_in[8];
    p.qkv_bnv  = (const float*)d_in[9];
    p.qkv_pw   = (const float*)d_in[10];
    p.position = (const float*)d_in[11];
    p.c1d_w    = (const float*)d_in[12];
    p.c1d_b    = (const float*)d_in[13];
    p.lin_w    = (const float*)d_in[14];
    p.lin_b    = (const float*)d_in[15];
    p.f1_w     = (const float*)d_in[16];
    p.f1_b     = (const float*)d_in[17];
    p.fdw_w    = (const float*)d_in[18];
    p.fdw_b    = (const float*)d_in[19];
    p.f_bng    = (const float*)d_in[20];
    p.f_bnb    = (const float*)d_in[21];
    p.f_bnm    = (const float*)d_in[22];
    p.f_bnv    = (const float*)d_in[23];
    p.fpw_w    = (const float*)d_in[24];
    p.fpw_b    = (const float*)d_in[25];
    p.f2_w     = (const float*)d_in[26];
    p.f2_b     = (const float*)d_in[27];
    p.out      = (float*)d_out;

    int nb = in_sizes[0] / (16 * 512);   // 2048

    cudaFuncSetAttribute(encoder_kernel,
                         cudaFuncAttributeMaxDynamicSharedMemorySize, SMEM_BYTES);
    encoder_kernel<<<nb, NT, SMEM_BYTES>>>(p);
}